// round 11
// baseline (speedup 1.0000x reference)
#include <cuda_runtime.h>
#include <cuda_bf16.h>
#include <cooperative_groups.h>
#include <cstdint>

namespace cg = cooperative_groups;

// Problem constants (fixed by the dataset)
#define BB    8        // batch
#define TT    4096     // time steps
#define FF    512      // input features
#define CC    128      // reduced input
#define UU    256      // LSTM units
#define OO    64       // output features
#define G4    1024     // 4*U

// -------- scratch (device globals; no allocation allowed) --------
__device__ float g_xr[(size_t)BB * TT * CC];   // 16 MB
__device__ float g_z [(size_t)BB * TT * G4];   // 128 MB
__device__ float g_hs[(size_t)BB * TT * UU];   // 32 MB

// ---------------- packed f32x2 helpers ----------------
__device__ __forceinline__ unsigned long long packf2(float lo, float hi) {
    unsigned long long r;
    asm("mov.b64 %0, {%1, %2};" : "=l"(r) : "f"(lo), "f"(hi));
    return r;
}
__device__ __forceinline__ void fma2(unsigned long long& d,
                                     unsigned long long a,
                                     unsigned long long b) {
    asm("fma.rn.f32x2 %0, %1, %2, %0;" : "+l"(d) : "l"(a), "l"(b));
}
__device__ __forceinline__ float reduce2(unsigned long long d) {
    float lo, hi;
    asm("mov.b64 {%0, %1}, %2;" : "=f"(lo), "=f"(hi) : "l"(d));
    return lo + hi;
}

// ---------------- fast activations (MUFU-based, ~1e-7 rel err) ----------------
__device__ __forceinline__ float fsig(float x) {
    return 1.0f / (1.0f + __expf(-x));
}
__device__ __forceinline__ float ftanh(float x) {
    x = fminf(fmaxf(x, -15.0f), 15.0f);
    float e = __expf(2.0f * x);
    return (e - 1.0f) / (e + 1.0f);
}

// =====================================================================
// fp32 tiled GEMM with double-buffered SMEM pipeline (R9, measured-good)
// =====================================================================
template <int BM, int BN, int BK, int TM, int TN, int NT>
__global__ void __launch_bounds__(NT)
gemm_bias_kernel(const float* __restrict__ A, const float* __restrict__ Bm,
                 const float* __restrict__ bias, float* __restrict__ C,
                 int M, int N, int K) {
    static_assert(BM * BK / 4 == NT, "A-tile load = 1 float4/thread");
    __shared__ __align__(16) float As[2][BK][BM + 4];
    __shared__ __align__(16) float Bs[2][BK][BN];

    const int tid = threadIdx.x;
    const int tx = tid % (BN / TN);
    const int ty = tid / (BN / TN);
    const int rowBase = blockIdx.y * BM;
    const int colBase = blockIdx.x * BN;

    const int ar  = tid / (BK / 4);
    const int akc = (tid % (BK / 4)) * 4;
    const bool bAct = tid < (BK * BN / 4);
    const int br  = bAct ? tid / (BN / 4) : 0;
    const int bcc = bAct ? (tid % (BN / 4)) * 4 : 0;

    const float* aSrc = A + (size_t)(rowBase + ar) * K + akc;
    const float* bSrc = Bm + (size_t)br * N + colBase + bcc;

    float acc[TM][TN];
#pragma unroll
    for (int i = 0; i < TM; i++)
#pragma unroll
        for (int j = 0; j < TN; j++) acc[i][j] = 0.0f;

    const int nk = K / BK;

    float4 va = *(const float4*)aSrc;
    float4 vb = bAct ? *(const float4*)bSrc : make_float4(0, 0, 0, 0);
    As[0][akc + 0][ar] = va.x;
    As[0][akc + 1][ar] = va.y;
    As[0][akc + 2][ar] = va.z;
    As[0][akc + 3][ar] = va.w;
    if (bAct) *(float4*)&Bs[0][br][bcc] = vb;
    __syncthreads();

#pragma unroll 1
    for (int kt = 0; kt < nk; kt++) {
        const int cur = kt & 1;
        if (kt + 1 < nk) {
            va = *(const float4*)(aSrc + (size_t)(kt + 1) * BK);
            if (bAct) vb = *(const float4*)(bSrc + (size_t)(kt + 1) * BK * N);
        }

#pragma unroll
        for (int kk = 0; kk < BK; kk++) {
            float ra[TM], rb[TN];
#pragma unroll
            for (int i = 0; i < TM; i += 4)
                *(float4*)&ra[i] = *(const float4*)&As[cur][kk][ty * TM + i];
#pragma unroll
            for (int j = 0; j < TN; j += 4)
                *(float4*)&rb[j] = *(const float4*)&Bs[cur][kk][tx * TN + j];
#pragma unroll
            for (int i = 0; i < TM; i++)
#pragma unroll
                for (int j = 0; j < TN; j++)
                    acc[i][j] = fmaf(ra[i], rb[j], acc[i][j]);
        }

        if (kt + 1 < nk) {
            const int nxt = cur ^ 1;
            As[nxt][akc + 0][ar] = va.x;
            As[nxt][akc + 1][ar] = va.y;
            As[nxt][akc + 2][ar] = va.z;
            As[nxt][akc + 3][ar] = va.w;
            if (bAct) *(float4*)&Bs[nxt][br][bcc] = vb;
            __syncthreads();
        }
    }

#pragma unroll
    for (int i = 0; i < TM; i++) {
        int row = rowBase + ty * TM + i;
#pragma unroll
        for (int j = 0; j < TN; j += 4) {
            int col = colBase + tx * TN + j;
            float4 b4 = *(const float4*)&bias[col];
            float4 o;
            o.x = acc[i][j + 0] + b4.x;
            o.y = acc[i][j + 1] + b4.y;
            o.z = acc[i][j + 2] + b4.z;
            o.w = acc[i][j + 3] + b4.w;
            *(float4*)&C[(size_t)row * N + col] = o;
        }
    }
}

// =====================================================================
// LSTM recurrence — R1 mechanism/layout with a PHASE-MERGED epilogue:
// after the single part[] __syncthreads, warp 0 reads the partials of
// all 4 gates directly (8 conflict-free LDS), adds its own prefetched
// 4-stream z, computes activations + c/h update itself, and pushes h.
// One __syncthreads + one cluster.sync per step (was 2 + 1).
// Everything else (layout, w2, single-chain dot, mapped-pointer DSMEM
// stores) is byte-identical to the measured-best R1 config.
// =====================================================================
#define LSTM_NTH 256
#define CLSZ     8

__global__ void __cluster_dims__(CLSZ, 1, 1) __launch_bounds__(LSTM_NTH, 1)
lstm_kernel(const float* __restrict__ rec_kernel) {
    cg::cluster_group cluster = cg::this_cluster();
    const int rank  = cluster.block_rank();        // 0..7 within cluster
    const int batch = blockIdx.x / CLSZ;           // 0..7
    const int tid   = threadIdx.x;
    const int lane  = tid & 31;

    const int c  = tid & 127;   // gate-column within this CTA's 128-col slice
    const int s  = tid >> 7;    // K-half: 0 -> k[0,128), 1 -> k[128,256)
    const int g  = c >> 5;      // gate: 0=i,1=f,2=g,3=o
    const int lu = c & 31;      // local unit
    const int u  = rank * 32 + lu;
    const int colIdx = (g << 8) + u;               // column in [0,1024)

    __shared__ __align__(16) float hbuf[2][UU];
    __shared__ float part[2][128];

    // ---- load weight slice into registers as packed pairs (R1-exact) ----
    unsigned long long w2[64];
#pragma unroll
    for (int m = 0; m < 64; m++) {
        float a = rec_kernel[(size_t)(s * 128 + 2 * m)     * G4 + colIdx];
        float b = rec_kernel[(size_t)(s * 128 + 2 * m + 1) * G4 + colIdx];
        w2[m] = packf2(a, b);
    }

    // ---- precompute peer h-buffer pointers (used by warp 0) ----
    float* dst0[CLSZ];
    float* dst1[CLSZ];
#pragma unroll
    for (int r = 0; r < CLSZ; r++) {
        dst0[r] = (float*)cluster.map_shared_rank((void*)hbuf[0], r);
        dst1[r] = (float*)cluster.map_shared_rank((void*)hbuf[1], r);
    }

    // ---- init state ----
    for (int i = tid; i < 2 * UU; i += LSTM_NTH) ((float*)hbuf)[i] = 0.0f;
    float cst = 0.0f;   // cell state (warp-0 lanes)
    cluster.sync();     // everyone's buffers zeroed before any remote write

    // warp 0: 4 z-streams (one per gate, this lane's unit), prefetched 1 step
    const float* zrow = g_z + (size_t)batch * TT * G4;
    const int uw = rank * 32 + lane;               // unit owned by this lane
    float zin4[4] = {0.f, 0.f, 0.f, 0.f};
    if (tid < 32) {
#pragma unroll
        for (int gt = 0; gt < 4; gt++)
            zin4[gt] = zrow[(gt << 8) + uw];       // t = 0
    }
    float* hsbase = g_hs + (size_t)batch * TT * UU;

    int p = 0;
#pragma unroll 1
    for (int t = 0; t < TT; t++) {
        // ---- z_partial = h[p] (my K-half) dot my weight column (R1-exact) ----
        unsigned long long acc2 = 0ULL;
        const float4* h4 = (const float4*)hbuf[p];
#pragma unroll
        for (int m = 0; m < 32; m++) {
            float4 hv = h4[s * 32 + m];
            fma2(acc2, w2[2 * m],     packf2(hv.x, hv.y));
            fma2(acc2, w2[2 * m + 1], packf2(hv.z, hv.w));
        }
        part[s][c] = reduce2(acc2);
        __syncthreads();                           // the ONLY intra-CTA barrier

        if (tid < 32) {
            // gather all 4 gates' partials for my unit (conflict-free LDS)
            float zi = part[0][      lane] + part[1][      lane] + zin4[0];
            float zf = part[0][ 32 + lane] + part[1][ 32 + lane] + zin4[1];
            float zg = part[0][ 64 + lane] + part[1][ 64 + lane] + zin4[2];
            float zo = part[0][ 96 + lane] + part[1][ 96 + lane] + zin4[3];

            // prefetch next step's z early (hidden behind MUFU chain)
            if (t + 1 < TT) {
                const float* znext = zrow + (size_t)(t + 1) * G4;
#pragma unroll
                for (int gt = 0; gt < 4; gt++)
                    zin4[gt] = __ldg(&znext[(gt << 8) + uw]);
            }

            float ai = fsig(zi);
            float af = fsig(zf);
            float ag = ftanh(zg);
            float ao = fsig(zo);
            cst = af * cst + ai * ag;
            float hval = ao * ftanh(cst);

            float** dst = (p == 0) ? dst1 : dst0;  // write next buffer
#pragma unroll
            for (int r = 0; r < CLSZ; r++) dst[r][uw] = hval;
            hsbase[(size_t)t * UU + uw] = hval;    // off the DSMEM critical path
        }
        cluster.sync();   // release DSMEM h-writes, all CTAs step together
        p ^= 1;
    }
}

// =====================================================================
// Launch
// =====================================================================
extern "C" void kernel_launch(void* const* d_in, const int* in_sizes, int n_in,
                              void* d_out, int out_size) {
    const float* x          = (const float*)d_in[0];  // [8,4096,512]
    const float* w_in       = (const float*)d_in[1];  // [512,128]
    const float* b_in       = (const float*)d_in[2];  // [128]
    const float* kern       = (const float*)d_in[3];  // [128,1024]
    const float* rec_kernel = (const float*)d_in[4];  // [256,1024]
    const float* bias       = (const float*)d_in[5];  // [1024]
    const float* w_out      = (const float*)d_in[6];  // [256,64]
    const float* b_out      = (const float*)d_in[7];  // [64]
    float* out = (float*)d_out;                       // [8,4096,64]

    float* xr = nullptr;
    float* zz = nullptr;
    float* hs = nullptr;
    cudaGetSymbolAddress((void**)&xr, g_xr);
    cudaGetSymbolAddress((void**)&zz, g_z);
    cudaGetSymbolAddress((void**)&hs, g_hs);

    const int M = BB * TT;  // 32768

    // 1) xr = x @ w_in + b_in       [32768,512] x [512,128]
    gemm_bias_kernel<128, 128, 8, 8, 8, 256>
        <<<dim3(CC / 128, M / 128), 256>>>(x, w_in, b_in, xr, M, CC, FF);

    // 2) z = xr @ kernel + bias     [32768,128] x [128,1024]
    gemm_bias_kernel<128, 128, 8, 8, 8, 256>
        <<<dim3(G4 / 128, M / 128), 256>>>(xr, kern, bias, zz, M, G4, CC);

    // 3) LSTM recurrence: 8 clusters x 8 CTAs
    lstm_kernel<<<BB * CLSZ, LSTM_NTH>>>(rec_kernel);

    // 4) out = hs @ w_out + b_out   [32768,256] x [256,64]
    gemm_bias_kernel<128, 64, 8, 8, 4, 256>
        <<<dim3(OO / 64, M / 128), 256>>>(hs, w_out, b_out, out, M, OO, UU);
}

// round 14
// speedup vs baseline: 1.2153x; 1.2153x over previous
#include <cuda_runtime.h>
#include <cuda_bf16.h>
#include <cooperative_groups.h>
#include <cstdint>

namespace cg = cooperative_groups;

// Problem constants (fixed by the dataset)
#define BB    8        // batch
#define TT    4096     // time steps
#define FF    512      // input features
#define CC    128      // reduced input
#define UU    256      // LSTM units
#define OO    64       // output features
#define G4    1024     // 4*U

#define NCH   8                // time chunks
#define TCH   (TT / NCH)       // 512 steps per chunk (even -> parity preserved)

// -------- scratch (device globals; no allocation allowed) --------
__device__ float g_xr [(size_t)BB * TT * CC];   // 16 MB
__device__ float g_z  [(size_t)BB * TT * G4];   // 128 MB
__device__ float g_hs [(size_t)BB * TT * UU];   // 32 MB
__device__ float g_cst[(size_t)BB * UU];        // cell state between chunks

// ---------------- packed f32x2 helpers ----------------
__device__ __forceinline__ unsigned long long packf2(float lo, float hi) {
    unsigned long long r;
    asm("mov.b64 %0, {%1, %2};" : "=l"(r) : "f"(lo), "f"(hi));
    return r;
}
__device__ __forceinline__ void fma2(unsigned long long& d,
                                     unsigned long long a,
                                     unsigned long long b) {
    asm("fma.rn.f32x2 %0, %1, %2, %0;" : "+l"(d) : "l"(a), "l"(b));
}
__device__ __forceinline__ float reduce2(unsigned long long d) {
    float lo, hi;
    asm("mov.b64 {%0, %1}, %2;" : "=f"(lo), "=f"(hi) : "l"(d));
    return lo + hi;
}

// ---------------- fast activations (MUFU-based, ~1e-7 rel err) ----------------
__device__ __forceinline__ float fsig(float x) {
    return 1.0f / (1.0f + __expf(-x));
}
__device__ __forceinline__ float ftanh(float x) {
    x = fminf(fmaxf(x, -15.0f), 15.0f);
    float e = __expf(2.0f * x);
    return (e - 1.0f) / (e + 1.0f);
}

// =====================================================================
// GEMM body (R9 double-buffered pipeline, measured-good)
// =====================================================================
template <int BM, int BN, int BK, int TM, int TN, int NT>
__device__ __forceinline__ void gemm_body(
    const float* __restrict__ A, const float* __restrict__ Bm,
    const float* __restrict__ bias, float* __restrict__ C,
    int M, int N, int K, int bxv, int byv) {

    __shared__ __align__(16) float As[2][BK][BM + 4];
    __shared__ __align__(16) float Bs[2][BK][BN];

    const int tid = threadIdx.x;
    const int tx = tid % (BN / TN);
    const int ty = tid / (BN / TN);
    const int rowBase = byv * BM;
    const int colBase = bxv * BN;

    const int ar  = tid / (BK / 4);
    const int akc = (tid % (BK / 4)) * 4;
    const bool bAct = tid < (BK * BN / 4);
    const int br  = bAct ? tid / (BN / 4) : 0;
    const int bcc = bAct ? (tid % (BN / 4)) * 4 : 0;

    const float* aSrc = A + (size_t)(rowBase + ar) * K + akc;
    const float* bSrc = Bm + (size_t)br * N + colBase + bcc;

    float acc[TM][TN];
#pragma unroll
    for (int i = 0; i < TM; i++)
#pragma unroll
        for (int j = 0; j < TN; j++) acc[i][j] = 0.0f;

    const int nk = K / BK;

    float4 va = *(const float4*)aSrc;
    float4 vb = bAct ? *(const float4*)bSrc : make_float4(0, 0, 0, 0);
    As[0][akc + 0][ar] = va.x;
    As[0][akc + 1][ar] = va.y;
    As[0][akc + 2][ar] = va.z;
    As[0][akc + 3][ar] = va.w;
    if (bAct) *(float4*)&Bs[0][br][bcc] = vb;
    __syncthreads();

#pragma unroll 1
    for (int kt = 0; kt < nk; kt++) {
        const int cur = kt & 1;
        if (kt + 1 < nk) {
            va = *(const float4*)(aSrc + (size_t)(kt + 1) * BK);
            if (bAct) vb = *(const float4*)(bSrc + (size_t)(kt + 1) * BK * N);
        }

#pragma unroll
        for (int kk = 0; kk < BK; kk++) {
            float ra[TM], rb[TN];
#pragma unroll
            for (int i = 0; i < TM; i += 4)
                *(float4*)&ra[i] = *(const float4*)&As[cur][kk][ty * TM + i];
#pragma unroll
            for (int j = 0; j < TN; j += 4)
                *(float4*)&rb[j] = *(const float4*)&Bs[cur][kk][tx * TN + j];
#pragma unroll
            for (int i = 0; i < TM; i++)
#pragma unroll
                for (int j = 0; j < TN; j++)
                    acc[i][j] = fmaf(ra[i], rb[j], acc[i][j]);
        }

        if (kt + 1 < nk) {
            const int nxt = cur ^ 1;
            As[nxt][akc + 0][ar] = va.x;
            As[nxt][akc + 1][ar] = va.y;
            As[nxt][akc + 2][ar] = va.z;
            As[nxt][akc + 3][ar] = va.w;
            if (bAct) *(float4*)&Bs[nxt][br][bcc] = vb;
            __syncthreads();
        }
    }

#pragma unroll
    for (int i = 0; i < TM; i++) {
        int row = rowBase + ty * TM + i;
#pragma unroll
        for (int j = 0; j < TN; j += 4) {
            int col = colBase + tx * TN + j;
            float4 b4 = *(const float4*)&bias[col];
            float4 o;
            o.x = acc[i][j + 0] + b4.x;
            o.y = acc[i][j + 1] + b4.y;
            o.z = acc[i][j + 2] + b4.z;
            o.w = acc[i][j + 3] + b4.w;
            *(float4*)&C[(size_t)row * N + col] = o;
        }
    }
}

// Chunked GEMM wrappers: blockIdx.y in [0,32) -> batch b = by>>2, band
// tl = by&3; global M-tile = b*(TT/128) + chunk*(TCH/128) + tl.
__device__ __forceinline__ int chunk_by(int chunk) {
    const int b  = blockIdx.y >> 2;
    const int tl = blockIdx.y & 3;
    return b * (TT / 128) + chunk * (TCH / 128) + tl;
}

__global__ void __launch_bounds__(256)
g1_chunk_kernel(const float* __restrict__ x, const float* __restrict__ w_in,
                const float* __restrict__ b_in, int chunk) {
    gemm_body<128, 128, 8, 8, 8, 256>(x, w_in, b_in, g_xr,
                                      BB * TT, CC, FF, blockIdx.x, chunk_by(chunk));
}
__global__ void __launch_bounds__(256)
g2_chunk_kernel(const float* __restrict__ kern, const float* __restrict__ bias,
                int chunk) {
    gemm_body<128, 128, 8, 8, 8, 256>(g_xr, kern, bias, g_z,
                                      BB * TT, G4, CC, blockIdx.x, chunk_by(chunk));
}
__global__ void __launch_bounds__(256)
g3_chunk_kernel(const float* __restrict__ w_out, const float* __restrict__ b_out,
                float* __restrict__ out, int chunk) {
    gemm_body<128, 64, 8, 8, 4, 256>(g_hs, w_out, b_out, out,
                                     BB * TT, OO, UU, blockIdx.x, chunk_by(chunk));
}

// =====================================================================
// LSTM chunk kernel — R1-EXACT step body, time range [t0, t0+TCH).
// State across chunks: c via g_cst (warp-0 save/restore), h(t0-1) via
// g_hs. Chunk boundaries are kernel boundaries -> graph edges provide
// all cross-kernel ordering/visibility. t0 even -> parity matches R1.
// =====================================================================
#define LSTM_NTH 256
#define CLSZ     8

__global__ void __cluster_dims__(CLSZ, 1, 1) __launch_bounds__(LSTM_NTH, 1)
lstm_chunk_kernel(const float* __restrict__ rec_kernel, int t0) {
    cg::cluster_group cluster = cg::this_cluster();
    const int rank  = cluster.block_rank();        // 0..7 within cluster
    const int batch = blockIdx.x / CLSZ;           // 0..7
    const int tid   = threadIdx.x;

    const int c  = tid & 127;   // gate-column within this CTA's 128-col slice
    const int s  = tid >> 7;    // K-half: 0 -> k[0,128), 1 -> k[128,256)
    const int g  = c >> 5;      // gate: 0=i,1=f,2=g,3=o
    const int lu = c & 31;      // local unit
    const int u  = rank * 32 + lu;
    const int colIdx = (g << 8) + u;               // column in [0,1024)

    __shared__ __align__(16) float hbuf[2][UU];
    __shared__ float part[2][128];
    __shared__ float act[128];

    // ---- load weight slice into registers as packed pairs ----
    unsigned long long w2[64];
#pragma unroll
    for (int m = 0; m < 64; m++) {
        float a = rec_kernel[(size_t)(s * 128 + 2 * m)     * G4 + colIdx];
        float b = rec_kernel[(size_t)(s * 128 + 2 * m + 1) * G4 + colIdx];
        w2[m] = packf2(a, b);
    }

    // ---- precompute peer h-buffer pointers (used by warp 0) ----
    float* dst0[CLSZ];
    float* dst1[CLSZ];
#pragma unroll
    for (int r = 0; r < CLSZ; r++) {
        dst0[r] = (float*)cluster.map_shared_rank((void*)hbuf[0], r);
        dst1[r] = (float*)cluster.map_shared_rank((void*)hbuf[1], r);
    }

    float* hsbase = g_hs + (size_t)batch * TT * UU;

    // ---- restore state: h(t0-1) into hbuf[0]; hbuf[1] zeroed ----
    if (t0 == 0) {
        for (int i = tid; i < 2 * UU; i += LSTM_NTH) ((float*)hbuf)[i] = 0.0f;
    } else {
        if (tid < UU) hbuf[0][tid] = hsbase[(size_t)(t0 - 1) * UU + tid];
        else          hbuf[1][tid - UU] = 0.0f;
    }
    float cst = 0.0f;   // cell state (warp-0 lanes)
    if (t0 > 0 && tid < 32) cst = g_cst[batch * UU + rank * 32 + tid];
    cluster.sync();     // state staged cluster-wide before any remote write

    const float* zbase = g_z + (size_t)batch * TT * G4 + colIdx;
    float zin = (s == 0) ? zbase[(size_t)t0 * G4] : 0.0f;   // prefetch t0
    const int t1 = t0 + TCH;

    int p = 0;          // t0 even -> h(t0-1) sits in hbuf[0], same as R1
#pragma unroll 1
    for (int t = t0; t < t1; t++) {
        // ---- z_partial = h[p] (my K-half) dot my weight column ----
        unsigned long long acc2 = 0ULL;
        const float4* h4 = (const float4*)hbuf[p];
#pragma unroll
        for (int m = 0; m < 32; m++) {
            float4 hv = h4[s * 32 + m];
            fma2(acc2, w2[2 * m],     packf2(hv.x, hv.y));
            fma2(acc2, w2[2 * m + 1], packf2(hv.z, hv.w));
        }
        part[s][c] = reduce2(acc2);
        __syncthreads();

        if (tid < 128) {
            float z = part[0][c] + part[1][c] + zin;
            if (t + 1 < t1) zin = zbase[(size_t)(t + 1) * G4];  // prefetch
            act[c] = (g == 2) ? ftanh(z) : fsig(z);
        }
        __syncthreads();

        if (tid < 32) {
            float ai = act[tid];
            float af = act[32 + tid];
            float ag = act[64 + tid];
            float ao = act[96 + tid];
            cst = af * cst + ai * ag;
            float hval = ao * ftanh(cst);
            int uw = rank * 32 + tid;
            hsbase[(size_t)t * UU + uw] = hval;
            float** dst = (p == 0) ? dst1 : dst0;   // write next buffer
#pragma unroll
            for (int r = 0; r < CLSZ; r++) dst[r][uw] = hval;
        }
        cluster.sync();   // release DSMEM h-writes, all CTAs step together
        p ^= 1;
    }

    // ---- save state for next chunk ----
    if (tid < 32) g_cst[batch * UU + rank * 32 + tid] = cst;
}

// =====================================================================
// Launch — chunked pipeline with stream/event overlap (host-side sync
// only; captured into the graph as dependency edges).
//   streamB: G1c_k -> G2c_k -> evG2[k]   (k = 0..7), then
//            wait evL[k] -> G3c_k, finally evEnd
//   stream0: wait evG2[k] -> LSTM_k -> evL[k], finally wait evEnd
// =====================================================================
extern "C" void kernel_launch(void* const* d_in, const int* in_sizes, int n_in,
                              void* d_out, int out_size) {
    const float* x          = (const float*)d_in[0];  // [8,4096,512]
    const float* w_in       = (const float*)d_in[1];  // [512,128]
    const float* b_in       = (const float*)d_in[2];  // [128]
    const float* kern       = (const float*)d_in[3];  // [128,1024]
    const float* rec_kernel = (const float*)d_in[4];  // [256,1024]
    const float* bias       = (const float*)d_in[5];  // [1024]
    const float* w_out      = (const float*)d_in[6];  // [256,64]
    const float* b_out      = (const float*)d_in[7];  // [64]
    float* out = (float*)d_out;                       // [8,4096,64]

    // one-time resource init (first call is the uncaptured correctness run;
    // no device memory is allocated, and the enqueued work is identical on
    // every call)
    static cudaStream_t sB = nullptr;
    static cudaEvent_t evStart = nullptr, evEnd = nullptr;
    static cudaEvent_t evG2[NCH], evL[NCH];
    if (sB == nullptr) {
        cudaStreamCreateWithFlags(&sB, cudaStreamNonBlocking);
        cudaEventCreateWithFlags(&evStart, cudaEventDisableTiming);
        cudaEventCreateWithFlags(&evEnd, cudaEventDisableTiming);
        for (int k = 0; k < NCH; k++) {
            cudaEventCreateWithFlags(&evG2[k], cudaEventDisableTiming);
            cudaEventCreateWithFlags(&evL[k], cudaEventDisableTiming);
        }
    }

    // fork streamB off the capture-origin (legacy) stream
    cudaEventRecord(evStart, 0);
    cudaStreamWaitEvent(sB, evStart, 0);

    // producer chain: per-chunk GEMM1 -> GEMM2, signal evG2[k]
    for (int k = 0; k < NCH; k++) {
        g1_chunk_kernel<<<dim3(1, 32), 256, 0, sB>>>(x, w_in, b_in, k);
        g2_chunk_kernel<<<dim3(8, 32), 256, 0, sB>>>(kern, bias, k);
        cudaEventRecord(evG2[k], sB);
    }

    // consumer chain on the origin stream: LSTM chunk k after its z chunk
    for (int k = 0; k < NCH; k++) {
        cudaStreamWaitEvent(0, evG2[k], 0);
        lstm_chunk_kernel<<<BB * CLSZ, LSTM_NTH>>>(rec_kernel, k * TCH);
        cudaEventRecord(evL[k], 0);
    }

    // output GEMM chunks overlap with later LSTM chunks
    for (int k = 0; k < NCH; k++) {
        cudaStreamWaitEvent(sB, evL[k], 0);
        g3_chunk_kernel<<<dim3(1, 32), 256, 0, sB>>>(w_out, b_out, out, k);
    }
    cudaEventRecord(evEnd, sB);
    cudaStreamWaitEvent(0, evEnd, 0);   // rejoin: origin stream sees all work
}